// round 17
// baseline (speedup 1.0000x reference)
#include <cuda_runtime.h>
#include <cuda_fp8.h>
#include <stdint.h>

#define NR 8192
#define DD 512
#define BM 128
#define BKB 64               // k bytes (fp8 elems) per chunk
#define NKT (DD / BKB)       // 8 k-chunks
#define NBLK (NR / BM)       // 64
#define NTRI (NBLK * (NBLK + 1) / 2)   // 2080 tiles
#define STAGES 4
#define SSTB 80                        // smem row stride bytes (conflict-free ldmatrix)
#define TILE_SMEM (BM * SSTB)          // 10240
#define STAGE_SMEM (2 * TILE_SMEM)     // 20480
#define SMEM_TOTAL (STAGES * STAGE_SMEM)  // 81920
#define RBLK 256                       // reduce blocks

// ---- device scratch ----
__device__ __align__(16) uint8_t g_ne[NR * DD];   // e4m3 normalized embeddings
__device__ float g_pos[NR];
__device__ float g_Spart[NBLK][NR];
__device__ float g_blocksum[RBLK];
__device__ int g_cnt;   // zero-init; self-resets each run

// ============================================================
// Kernel A: normalize -> e4m3 (R16, unchanged)
// ============================================================
__global__ void __launch_bounds__(256) norm_kernel(const float* __restrict__ emb,
                                                   const float* __restrict__ tgt) {
    const int w = threadIdx.x >> 5;
    const int l = threadIdx.x & 31;
    const int row0 = (blockIdx.x * 8 + w) * 2;

    const float4* e0 = reinterpret_cast<const float4*>(emb + (size_t)row0 * DD);
    const float4* t0 = reinterpret_cast<const float4*>(tgt + (size_t)row0 * DD);
    const float4* e1 = e0 + DD / 4;
    const float4* t1 = t0 + DD / 4;

    float4 a0[4], a1[4], b0[4], b1[4];
#pragma unroll
    for (int j = 0; j < 4; j++) {
        a0[j] = __ldg(e0 + l + 32 * j);
        a1[j] = __ldg(e1 + l + 32 * j);
        b0[j] = __ldg(t0 + l + 32 * j);
        b1[j] = __ldg(t1 + l + 32 * j);
    }

    float ee0 = 0.f, tt0 = 0.f, et0 = 0.f, ee1 = 0.f, tt1 = 0.f, et1 = 0.f;
#pragma unroll
    for (int j = 0; j < 4; j++) {
        ee0 += a0[j].x*a0[j].x + a0[j].y*a0[j].y + a0[j].z*a0[j].z + a0[j].w*a0[j].w;
        tt0 += b0[j].x*b0[j].x + b0[j].y*b0[j].y + b0[j].z*b0[j].z + b0[j].w*b0[j].w;
        et0 += a0[j].x*b0[j].x + a0[j].y*b0[j].y + a0[j].z*b0[j].z + a0[j].w*b0[j].w;
        ee1 += a1[j].x*a1[j].x + a1[j].y*a1[j].y + a1[j].z*a1[j].z + a1[j].w*a1[j].w;
        tt1 += b1[j].x*b1[j].x + b1[j].y*b1[j].y + b1[j].z*b1[j].z + b1[j].w*b1[j].w;
        et1 += a1[j].x*b1[j].x + a1[j].y*b1[j].y + a1[j].z*b1[j].z + a1[j].w*b1[j].w;
    }
#pragma unroll
    for (int o = 16; o > 0; o >>= 1) {
        ee0 += __shfl_xor_sync(0xFFFFFFFFu, ee0, o);
        tt0 += __shfl_xor_sync(0xFFFFFFFFu, tt0, o);
        et0 += __shfl_xor_sync(0xFFFFFFFFu, et0, o);
        ee1 += __shfl_xor_sync(0xFFFFFFFFu, ee1, o);
        tt1 += __shfl_xor_sync(0xFFFFFFFFu, tt1, o);
        et1 += __shfl_xor_sync(0xFFFFFFFFu, et1, o);
    }

    float inv0 = rsqrtf(ee0);
    float inv1 = rsqrtf(ee1);
    if (l == 0) {
        g_pos[row0]     = et0 * inv0 * rsqrtf(tt0);
        g_pos[row0 + 1] = et1 * inv1 * rsqrtf(tt1);
    }

    uint32_t* o0 = reinterpret_cast<uint32_t*>(g_ne) + (size_t)row0 * (DD / 4);
    uint32_t* o1 = o0 + DD / 4;
#pragma unroll
    for (int j = 0; j < 4; j++) {
        uint16_t lo, hi;
        asm("cvt.rn.satfinite.e4m3x2.f32 %0, %1, %2;"
            : "=h"(lo) : "f"(a0[j].y * inv0), "f"(a0[j].x * inv0));
        asm("cvt.rn.satfinite.e4m3x2.f32 %0, %1, %2;"
            : "=h"(hi) : "f"(a0[j].w * inv0), "f"(a0[j].z * inv0));
        o0[l + 32 * j] = (uint32_t)lo | ((uint32_t)hi << 16);
        asm("cvt.rn.satfinite.e4m3x2.f32 %0, %1, %2;"
            : "=h"(lo) : "f"(a1[j].y * inv1), "f"(a1[j].x * inv1));
        asm("cvt.rn.satfinite.e4m3x2.f32 %0, %1, %2;"
            : "=h"(hi) : "f"(a1[j].w * inv1), "f"(a1[j].z * inv1));
        o1[l + 32 * j] = (uint32_t)lo | ((uint32_t)hi << 16);
    }
}

// ============================================================
// MMA / cp.async helpers
// ============================================================
__device__ __forceinline__ void ldsm_x4(uint32_t& r0, uint32_t& r1, uint32_t& r2, uint32_t& r3,
                                        uint32_t addr) {
    asm volatile("ldmatrix.sync.aligned.m8n8.x4.shared.b16 {%0,%1,%2,%3}, [%4];"
                 : "=r"(r0), "=r"(r1), "=r"(r2), "=r"(r3) : "r"(addr));
}
__device__ __forceinline__ void mma_fp8(float c[4], const uint32_t a[4], uint32_t b0, uint32_t b1) {
    asm volatile(
        "mma.sync.aligned.m16n8k32.row.col.f32.e4m3.e4m3.f32 "
        "{%0,%1,%2,%3}, {%4,%5,%6,%7}, {%8,%9}, {%0,%1,%2,%3};"
        : "+f"(c[0]), "+f"(c[1]), "+f"(c[2]), "+f"(c[3])
        : "r"(a[0]), "r"(a[1]), "r"(a[2]), "r"(a[3]), "r"(b0), "r"(b1));
}
__device__ __forceinline__ void cp16(uint32_t dst, const void* src) {
    asm volatile("cp.async.cg.shared.global [%0], [%1], 16;" :: "r"(dst), "l"(src));
}
__device__ __forceinline__ void cp_commit() {
    asm volatile("cp.async.commit_group;" ::: "memory");
}
template <int N>
__device__ __forceinline__ void cp_wait() {
    asm volatile("cp.async.wait_group %0;" :: "n"(N) : "memory");
}

// ============================================================
// Kernel B: upper-triangle fp8 GEMM + exp(2x) row/col sums
//   paired-chunk mainloop: 2 k-chunks per sync (4 syncs total)
// ============================================================
__global__ void __launch_bounds__(256, 2) gemm_lse_kernel() {
    extern __shared__ char smem[];
    const uint32_t sb = (uint32_t)__cvta_generic_to_shared(smem);

    const int tid = threadIdx.x;
    const int lane = tid & 31;
    const int wid = tid >> 5;
    const int warp_m = wid >> 1;
    const int warp_n = wid & 1;
    const int ksel = wid & 1;

    int t = blockIdx.x;
    int bi = (int)(64.5f - sqrtf(64.5f * 64.5f - 2.0f * (float)t));
    if (bi < 0) bi = 0;
    if (bi > 63) bi = 63;
#define TRI_S(b) ((b) * 64 - ((b) * ((b) - 1)) / 2)
    while (bi > 0 && TRI_S(bi) > t) bi--;
    while (bi < 63 && TRI_S(bi + 1) <= t) bi++;
    const int bj = bi + (t - TRI_S(bi));
    const bool diag = (bi == bj);

    const uint8_t* gA = g_ne + (size_t)bi * BM * DD;
    const uint8_t* gB = g_ne + (size_t)bj * BM * DD;

    const int r0c = tid >> 2;
    const int r1c = (tid + 256) >> 2;
    const int kc0 = (tid & 3) * 16;

    const int lrow = lane & 15;
    const int lkb  = (lane >> 4) * 16;
    const uint32_t aoff0 = (uint32_t)((warp_m * 32 + lrow) * SSTB + lkb);
    const uint32_t aoff1 = aoff0 + 16 * SSTB;
    uint32_t boff[4];
#pragma unroll
    for (int nj = 0; nj < 4; nj++)
        boff[nj] = (uint32_t)((warp_n * 64 + nj * 16 + lrow) * SSTB + lkb) + TILE_SMEM;

    float acc[2][8][4];
#pragma unroll
    for (int mi = 0; mi < 2; mi++)
#pragma unroll
        for (int ni = 0; ni < 8; ni++)
#pragma unroll
            for (int k = 0; k < 4; k++) acc[mi][ni][k] = 0.f;

    // ---- prologue: chunks 0,1 (one group) ----
#pragma unroll
    for (int p = 0; p < 2; p++) {
        uint32_t base = sb + p * STAGE_SMEM;
        cp16(base + r0c * SSTB + kc0, gA + (size_t)r0c * DD + p * BKB + kc0);
        cp16(base + r1c * SSTB + kc0, gA + (size_t)r1c * DD + p * BKB + kc0);
        cp16(base + TILE_SMEM + r0c * SSTB + kc0, gB + (size_t)r0c * DD + p * BKB + kc0);
        cp16(base + TILE_SMEM + r1c * SSTB + kc0, gB + (size_t)r1c * DD + p * BKB + kc0);
    }
    cp_commit();

#pragma unroll
    for (int dk = 0; dk < NKT / 2; dk++) {
        const int c0 = 2 * dk;
        const int c1 = c0 + 1;
        cp_wait<0>();          // previous group done (this group's loads had a full
        __syncthreads();       // iteration of compute to land)

        uint32_t base0 = sb + (c0 & (STAGES - 1)) * STAGE_SMEM;
        uint32_t base1 = sb + (c1 & (STAGES - 1)) * STAGE_SMEM;
        const uint32_t o0 = (uint32_t)ksel * 32;
        const uint32_t o1 = o0 ^ 32;

        // critical-path ldsm for chunk c0 / first half
        uint32_t a[2][4], b[4][4];
        ldsm_x4(a[0][0], a[0][1], a[0][2], a[0][3], base0 + aoff0 + o0);
        ldsm_x4(a[1][0], a[1][1], a[1][2], a[1][3], base0 + aoff1 + o0);
#pragma unroll
        for (int nj = 0; nj < 4; nj++)
            ldsm_x4(b[nj][0], b[nj][1], b[nj][2], b[nj][3], base0 + boff[nj] + o0);

        // prefetch chunks c0+2, c1+2 (buffers consumed last iteration)
        if (c0 + 2 < NKT) {
#pragma unroll
            for (int q = 0; q < 2; q++) {
                const int kl = c0 + 2 + q;
                uint32_t lb = sb + (kl & (STAGES - 1)) * STAGE_SMEM;
                cp16(lb + r0c * SSTB + kc0, gA + (size_t)r0c * DD + kl * BKB + kc0);
                cp16(lb + r1c * SSTB + kc0, gA + (size_t)r1c * DD + kl * BKB + kc0);
                cp16(lb + TILE_SMEM + r0c * SSTB + kc0, gB + (size_t)r0c * DD + kl * BKB + kc0);
                cp16(lb + TILE_SMEM + r1c * SSTB + kc0, gB + (size_t)r1c * DD + kl * BKB + kc0);
            }
        }
        cp_commit();

        // chunk c0 / first half mma
#pragma unroll
        for (int mi = 0; mi < 2; mi++)
#pragma unroll
            for (int ni = 0; ni < 8; ni++)
                mma_fp8(acc[mi][ni], a[mi], b[ni >> 1][ni & 1], b[ni >> 1][(ni & 1) + 2]);

        // chunk c0 / second half
        ldsm_x4(a[0][0], a[0][1], a[0][2], a[0][3], base0 + aoff0 + o1);
        ldsm_x4(a[1][0], a[1][1], a[1][2], a[1][3], base0 + aoff1 + o1);
#pragma unroll
        for (int nj = 0; nj < 4; nj++)
            ldsm_x4(b[nj][0], b[nj][1], b[nj][2], b[nj][3], base0 + boff[nj] + o1);
#pragma unroll
        for (int mi = 0; mi < 2; mi++)
#pragma unroll
            for (int ni = 0; ni < 8; ni++)
                mma_fp8(acc[mi][ni], a[mi], b[ni >> 1][ni & 1], b[ni >> 1][(ni & 1) + 2]);

        // chunk c1 / first half
        ldsm_x4(a[0][0], a[0][1], a[0][2], a[0][3], base1 + aoff0 + o0);
        ldsm_x4(a[1][0], a[1][1], a[1][2], a[1][3], base1 + aoff1 + o0);
#pragma unroll
        for (int nj = 0; nj < 4; nj++)
            ldsm_x4(b[nj][0], b[nj][1], b[nj][2], b[nj][3], base1 + boff[nj] + o0);
#pragma unroll
        for (int mi = 0; mi < 2; mi++)
#pragma unroll
            for (int ni = 0; ni < 8; ni++)
                mma_fp8(acc[mi][ni], a[mi], b[ni >> 1][ni & 1], b[ni >> 1][(ni & 1) + 2]);

        // chunk c1 / second half
        ldsm_x4(a[0][0], a[0][1], a[0][2], a[0][3], base1 + aoff0 + o1);
        ldsm_x4(a[1][0], a[1][1], a[1][2], a[1][3], base1 + aoff1 + o1);
#pragma unroll
        for (int nj = 0; nj < 4; nj++)
            ldsm_x4(b[nj][0], b[nj][1], b[nj][2], b[nj][3], base1 + boff[nj] + o1);
#pragma unroll
        for (int mi = 0; mi < 2; mi++)
#pragma unroll
            for (int ni = 0; ni < 8; ni++)
                mma_fp8(acc[mi][ni], a[mi], b[ni >> 1][ni & 1], b[ni >> 1][(ni & 1) + 2]);
    }

    // ---- epilogue ----
#pragma unroll
    for (int mi = 0; mi < 2; mi++)
#pragma unroll
        for (int ni = 0; ni < 8; ni++)
#pragma unroll
            for (int k = 0; k < 4; k++) {
                float x = acc[mi][ni][k];
                acc[mi][ni][k] = __expf(x + x);
            }

    float* rowbuf = (float*)smem;               // [2][128]
    float* colbuf = (float*)(smem + 1024);      // [4][128]
    __syncthreads();

#pragma unroll
    for (int mi = 0; mi < 2; mi++) {
        float r0 = 0.f, r1 = 0.f;
#pragma unroll
        for (int ni = 0; ni < 8; ni++) {
            r0 += acc[mi][ni][0] + acc[mi][ni][1];
            r1 += acc[mi][ni][2] + acc[mi][ni][3];
        }
        r0 += __shfl_xor_sync(0xFFFFFFFFu, r0, 1);
        r0 += __shfl_xor_sync(0xFFFFFFFFu, r0, 2);
        r1 += __shfl_xor_sync(0xFFFFFFFFu, r1, 1);
        r1 += __shfl_xor_sync(0xFFFFFFFFu, r1, 2);
        if ((lane & 3) == 0) {
            int rr = warp_m * 32 + mi * 16 + (lane >> 2);
            rowbuf[warp_n * 128 + rr] = r0;
            rowbuf[warp_n * 128 + rr + 8] = r1;
        }
    }

    if (!diag) {
#pragma unroll
        for (int ni = 0; ni < 8; ni++) {
            float ce = acc[0][ni][0] + acc[0][ni][2] + acc[1][ni][0] + acc[1][ni][2];
            float co = acc[0][ni][1] + acc[0][ni][3] + acc[1][ni][1] + acc[1][ni][3];
            ce += __shfl_xor_sync(0xFFFFFFFFu, ce, 4);
            ce += __shfl_xor_sync(0xFFFFFFFFu, ce, 8);
            ce += __shfl_xor_sync(0xFFFFFFFFu, ce, 16);
            co += __shfl_xor_sync(0xFFFFFFFFu, co, 4);
            co += __shfl_xor_sync(0xFFFFFFFFu, co, 8);
            co += __shfl_xor_sync(0xFFFFFFFFu, co, 16);
            if (lane < 4) {
                int cc = warp_n * 64 + ni * 8 + lane * 2;
                colbuf[warp_m * 128 + cc] = ce;
                colbuf[warp_m * 128 + cc + 1] = co;
            }
        }
    }
    __syncthreads();

    if (tid < 128) {
        g_Spart[bj][bi * BM + tid] = rowbuf[tid] + rowbuf[128 + tid];
        if (!diag)
            g_Spart[bi][bj * BM + tid] =
                colbuf[tid] + colbuf[128 + tid] + colbuf[256 + tid] + colbuf[384 + tid];
    }
}

// ============================================================
// Kernel C: coalesced per-row combine + final  [R13, unchanged]
// ============================================================
__global__ void reduce_kernel(float* __restrict__ out) {
    const int tid = threadIdx.x;
    const int wid = tid >> 5;
    const int lane = tid & 31;
    const int row = blockIdx.x * 32 + lane;

    float s = 0.f;
#pragma unroll
    for (int k = 0; k < 8; k++) s += g_Spart[wid * 8 + k][row];   // coalesced per warp

    __shared__ float sp[8][32];
    __shared__ int slast;
    sp[wid][lane] = s;
    __syncthreads();

    if (wid == 0) {
        float tot = sp[0][lane] + sp[1][lane] + sp[2][lane] + sp[3][lane]
                  + sp[4][lane] + sp[5][lane] + sp[6][lane] + sp[7][lane];
        float v = logf(tot) - 2.f * g_pos[row];
#pragma unroll
        for (int o = 16; o > 0; o >>= 1) v += __shfl_xor_sync(0xFFFFFFFFu, v, o);
        if (lane == 0) {
            g_blocksum[blockIdx.x] = v;
            __threadfence();
            int prev = atomicAdd(&g_cnt, 1);
            slast = (prev == RBLK - 1) ? 1 : 0;
        }
    }
    __syncthreads();
    if (slast && tid < 32) {
        __threadfence();
        float x = 0.f;
#pragma unroll
        for (int k = 0; k < RBLK / 32; k++) x += g_blocksum[tid * (RBLK / 32) + k];
#pragma unroll
        for (int o = 16; o > 0; o >>= 1) x += __shfl_xor_sync(0xFFFFFFFFu, x, o);
        if (tid == 0) {
            out[0] = x * (1.0f / (2.0f * NR));
            g_cnt = 0;   // reset for next graph replay
        }
    }
}

// ============================================================
extern "C" void kernel_launch(void* const* d_in, const int* in_sizes, int n_in,
                              void* d_out, int out_size) {
    const float* emb = (const float*)d_in[0];
    const float* tgt = (const float*)d_in[1];
    float* out = (float*)d_out;

    cudaFuncSetAttribute(gemm_lse_kernel, cudaFuncAttributeMaxDynamicSharedMemorySize, SMEM_TOTAL);

    norm_kernel<<<NR / 16, 256>>>(emb, tgt);
    gemm_lse_kernel<<<NTRI, 256, SMEM_TOTAL>>>();
    reduce_kernel<<<RBLK, 256>>>(out);
}